// round 16
// baseline (speedup 1.0000x reference)
#include <cuda_runtime.h>
#include <cuda_fp16.h>
#include <cstdint>
#include <math.h>

#define NQ 16384
#define NS 8192
#define D 64
#define NTILES 64          // support tiles of 128 rows
#define STEPS 10
#define NCTA (NQ / 128)    // 128 CTAs, 16 warps each
#define TILE_U32 12288     // 48KB per tile image
#define TILE_BYTES 49152

// ---------------- device globals (no allocations allowed) -------------------
__device__ float g_hhat[NQ * D];          // h = h_hat + q (pre-added)
__device__ float g_c[NQ * D];
__device__ float g_gx[NQ * 4 * D];        // [q][u][gate i,f,g,o]
__device__ float g_WihT[D * 4 * D];       // [d][row]
// Whh image (fp16 hi/lo) for mma tail:
//   i = jo*4096 + gate*1024 + ub*256 + ks*64 + g*8 + qq*2 + b   (hi; lo at +8192)
__device__ __align__(16) uint32_t g_WhhImg[16384];
// Per tile (12288 u32 = 48KB):
//  I1 (fp16 of s*log2e): u32[ks4][j8][g8][qq4][vec4]            (4096 u32)
//  V (readout, tf32): float4[j8][qq4][fslot64] at +4096, fslot = nb*8+g
__device__ __align__(16) uint32_t g_B[(size_t)NTILES * TILE_U32];

// ---------------- helpers ----------------------------------------------------
__device__ __forceinline__ uint32_t smem_u32(const void* p) {
    uint32_t a;
    asm("{ .reg .u64 t; cvta.to.shared.u64 t, %1; cvt.u32.u64 %0, t; }"
        : "=r"(a) : "l"(p));
    return a;
}
__device__ __forceinline__ void cp16(uint32_t saddr, const void* g) {
    asm volatile("cp.async.cg.shared.global [%0], [%1], 16;"
                 :: "r"(saddr), "l"(g) : "memory");
}
#define CP_COMMIT() asm volatile("cp.async.commit_group;" ::: "memory")
#define CP_WAIT0()  asm volatile("cp.async.wait_group 0;" ::: "memory")

__device__ __forceinline__ float tf32f(float v) {
    float r;
    asm("cvt.rna.tf32.f32 %0, %1;" : "=f"(r) : "f"(v));
    return r;
}
__device__ __forceinline__ float ex2(float x) {
    float r;
    asm("ex2.approx.f32 %0, %1;" : "=f"(r) : "f"(x));
    return r;
}
__device__ __forceinline__ uint32_t hpack(float v0, float v1) {
    __half2 h = __floats2half2_rn(v0, v1);
    return *reinterpret_cast<uint32_t*>(&h);
}
// exact 2-term fp16 split of (v0, v1)
__device__ __forceinline__ void hsplit(float v0, float v1,
                                       uint32_t& hi, uint32_t& lo) {
    __half2 h = __floats2half2_rn(v0, v1);
    hi = *reinterpret_cast<uint32_t*>(&h);
    float r0 = __half2float(__low2half(h));
    float r1 = __half2float(__high2half(h));
    lo = hpack(v0 - r0, v1 - r1);
}
__device__ __forceinline__ void mmah(float* c, const uint32_t* a,
                                     uint32_t b0, uint32_t b1) {
    asm volatile(
        "mma.sync.aligned.m16n8k16.row.col.f32.f16.f16.f32 "
        "{%0,%1,%2,%3}, {%4,%5,%6,%7}, {%8,%9}, {%0,%1,%2,%3};"
        : "+f"(c[0]), "+f"(c[1]), "+f"(c[2]), "+f"(c[3])
        : "r"(a[0]), "r"(a[1]), "r"(a[2]), "r"(a[3]), "r"(b0), "r"(b1));
}
__device__ __forceinline__ void mmatf(float* c, float a0, float a1, float a2,
                                      float a3, float b0, float b1) {
    asm volatile(
        "mma.sync.aligned.m16n8k8.row.col.f32.tf32.tf32.f32 "
        "{%0,%1,%2,%3}, {%4,%5,%6,%7}, {%8,%9}, {%0,%1,%2,%3};"
        : "+f"(c[0]), "+f"(c[1]), "+f"(c[2]), "+f"(c[3])
        : "r"(__float_as_uint(a0)), "r"(__float_as_uint(a1)),
          "r"(__float_as_uint(a2)), "r"(__float_as_uint(a3)),
          "r"(__float_as_uint(b0)), "r"(__float_as_uint(b1)));
}
__device__ __forceinline__ float sigf(float x) { return 1.f / (1.f + __expf(-x)); }

#define LOG2E 1.4426950408889634f
#define SHIFT2 46.0f   // constant shift in log2 domain (softmax-invariant)

// ---------------- prep: support images --------------------------------------
__global__ void prep_kernel(const float* __restrict__ support) {
    int t = blockIdx.x;
    const float* s = support + (size_t)t * 128 * D;
    uint32_t* dst = g_B + (size_t)t * TILE_U32;
    // I1: single fp16 of s*log2e
    for (int i = threadIdx.x; i < 4096; i += 256) {
        int vec = i & 3, qq = (i >> 2) & 3, g = (i >> 4) & 7;
        int j = (i >> 7) & 7, ks = (i >> 10) & 3;
        int r = 16 * j + g + ((vec & 2) ? 8 : 0);
        int f0 = ks * 16 + ((vec & 1) ? 8 : 0) + 2 * qq;
        dst[i] = hpack(s[r * 64 + f0] * LOG2E, s[r * 64 + f0 + 1] * LOG2E);
    }
    // V: tf32, float4-packed [j][qq][fslot][comp], comp = h*2+pr, fslot linear
    float* vd = (float*)(dst + 4096);
    for (int i = threadIdx.x; i < 8192; i += 256) {
        int comp = i & 3, base = i >> 2;
        int fslot = base & 63, qq = (base >> 6) & 3, j = (base >> 8) & 7;
        int pr = comp & 1, h = comp >> 1;
        int row = 16 * j + 8 * h + 2 * qq + pr;
        vd[i] = tf32f(s[row * 64 + fslot]);
    }
}

// ---------------- weight prep + gx (once) ------------------------------------
__global__ void prep_w_kernel(const float* __restrict__ W_ih,
                              const float* __restrict__ W_hh) {
    int i = blockIdx.x * blockDim.x + threadIdx.x;
    if (i < 256 * 64) {
        int r = i / D, d = i % D;
        g_WihT[d * 256 + r] = W_ih[i];
    }
    if (i < 8192) {
        int b = i & 1, qq = (i >> 1) & 3, g = (i >> 3) & 7;
        int ks = (i >> 6) & 3, ub = (i >> 8) & 3, gate = (i >> 10) & 3;
        int jo = (i >> 12) & 1;
        int n = gate * 64 + jo * 32 + ub * 8 + g;
        int k0 = ks * 16 + b * 8 + 2 * qq;
        uint32_t hi, lo;
        hsplit(W_hh[n * 64 + k0], W_hh[n * 64 + k0 + 1], hi, lo);
        g_WhhImg[i] = hi;
        g_WhhImg[i + 8192] = lo;
    }
}
__global__ void gx_kernel(const float* __restrict__ q,
                          const float* __restrict__ b_ih,
                          const float* __restrict__ b_hh) {
    __shared__ float qs[D];
    int qi = blockIdx.x, g = threadIdx.x;
    if (g < D) qs[g] = q[qi * D + g];
    __syncthreads();
    float acc = b_ih[g] + b_hh[g];
#pragma unroll
    for (int d = 0; d < D; d++)
        acc = fmaf(qs[d], __ldg(&g_WihT[d * 256 + g]), acc);
    g_gx[qi * 256 + (g & 63) * 4 + (g >> 6)] = acc;
}

// ---------------- fused attention + tensor-core LSTM tail --------------------
// smem: H 32KB | Ox 32KB | lx 512B(+pad) | Whh image 64KB  -> 132096 B
__global__ void __launch_bounds__(512, 1)
attn_kernel(const float* __restrict__ q, float* __restrict__ out,
            int first, int last) {
    extern __shared__ float sm[];
    float* Hs = sm;
    const int tid = threadIdx.x;
    const int w = tid >> 5, lane = tid & 31;
    const int g = lane >> 2, qq = lane & 3;
    const int wq = w & 7;          // query row-group
    const int jo = w >> 3;         // chunk parity / unit-half group
    const int mrow = wq * 16;
    const int qbase = blockIdx.x * 128;
    const uint32_t sb = smem_u32(sm);
    const uint32_t* Wsm = (const uint32_t*)(sm + 16640);   // byte 66560

    // prefetch Whh image to smem (one group; waited before LSTM tail)
    {
        const char* wsrc = (const char*)g_WhhImg + tid * 128;
        uint32_t wdst = sb + 66560 + tid * 128;
#pragma unroll
        for (int i = 0; i < 8; i++) cp16(wdst + i * 16, wsrc + i * 16);
        CP_COMMIT();
    }

    // H (pre-added h_hat + q stored in g_hhat)
    {
        const float4* src = first
            ? (const float4*)(q + (size_t)qbase * D)
            : (const float4*)(g_hhat + (size_t)qbase * D);
        float4* H4 = (float4*)Hs;
        for (int i = tid; i < 2048; i += 512) H4[i] = src[i];
    }
    __syncthreads();

    // A fragments for MMA1: single fp16 (B image carries log2e)
    uint32_t ahi[16], alo[16];
    {
        int row0 = mrow + g, row1 = mrow + g + 8;
#pragma unroll
        for (int ks = 0; ks < 4; ks++) {
            int cb = ks * 16 + 2 * qq;
            ahi[4 * ks + 0] = hpack(Hs[row0 * 64 + cb],     Hs[row0 * 64 + cb + 1]);
            ahi[4 * ks + 1] = hpack(Hs[row1 * 64 + cb],     Hs[row1 * 64 + cb + 1]);
            ahi[4 * ks + 2] = hpack(Hs[row0 * 64 + cb + 8], Hs[row0 * 64 + cb + 9]);
            ahi[4 * ks + 3] = hpack(Hs[row1 * 64 + cb + 8], Hs[row1 * 64 + cb + 9]);
        }
    }

    float O[32];
#pragma unroll
    for (int i = 0; i < 32; i++) O[i] = 0.f;
    float lacc0 = 0.f, lacc1 = 0.f;

    // per-warp streaming pointers (advance 48KB per tile); NO barriers in loop
    const char* pI1 = (const char*)g_B + jo * 512 + g * 64 + qq * 16;
    const char* pV  = (const char*)g_B + 16384 + jo * 4096 + qq * 1024 + g * 16;

#pragma unroll 1
    for (int t = 0; t < NTILES; t++) {
#pragma unroll
        for (int pc = 0; pc < 2; pc++) {
            const char* qI = pI1 + pc * 2048;
            const char* qV = pV + pc * 16384;
            // ---- MMA1 for chunk pair (jA=jo+4pc, jB=jA+2): 16 mma, 4 chains
            float cA0[4] = {0, 0, 0, 0}, cA1[4] = {0, 0, 0, 0};
            float cB0[4] = {0, 0, 0, 0}, cB1[4] = {0, 0, 0, 0};
#pragma unroll
            for (int ks = 0; ks < 4; ks++) {
                uint4 bA = __ldg((const uint4*)(qI + ks * 4096));
                uint4 bB = __ldg((const uint4*)(qI + ks * 4096 + 1024));
                mmah(cA0, ahi + 4 * ks, bA.x, bA.y);
                mmah(cB0, ahi + 4 * ks, bB.x, bB.y);
                mmah(cA1, ahi + 4 * ks, bA.z, bA.w);
                mmah(cB1, ahi + 4 * ks, bB.z, bB.w);
            }
            // ---- exp chunk A (exp2; B image pre-scaled by log2e)
            float pA0 = tf32f(ex2(cA0[0] - SHIFT2));
            float pA1 = tf32f(ex2(cA0[1] - SHIFT2));
            float pA2 = tf32f(ex2(cA0[2] - SHIFT2));
            float pA3 = tf32f(ex2(cA0[3] - SHIFT2));
            float pX0 = tf32f(ex2(cA1[0] - SHIFT2));
            float pX1 = tf32f(ex2(cA1[1] - SHIFT2));
            float pX2 = tf32f(ex2(cA1[2] - SHIFT2));
            float pX3 = tf32f(ex2(cA1[3] - SHIFT2));
            lacc0 += (pA0 + pA1) + (pX0 + pX1);
            lacc1 += (pA2 + pA3) + (pX2 + pX3);
            // ---- MMA2 chunk A
#pragma unroll
            for (int nb = 0; nb < 8; nb++) {
                float4 vb = __ldg((const float4*)(qV + nb * 128));
                mmatf(O + 4 * nb, pA0, pA2, pA1, pA3, vb.x, vb.y);
                mmatf(O + 4 * nb, pX0, pX2, pX1, pX3, vb.z, vb.w);
            }
            // ---- exp chunk B
            float pB0 = tf32f(ex2(cB0[0] - SHIFT2));
            float pB1 = tf32f(ex2(cB0[1] - SHIFT2));
            float pB2 = tf32f(ex2(cB0[2] - SHIFT2));
            float pB3 = tf32f(ex2(cB0[3] - SHIFT2));
            float pY0 = tf32f(ex2(cB1[0] - SHIFT2));
            float pY1 = tf32f(ex2(cB1[1] - SHIFT2));
            float pY2 = tf32f(ex2(cB1[2] - SHIFT2));
            float pY3 = tf32f(ex2(cB1[3] - SHIFT2));
            lacc0 += (pB0 + pB1) + (pY0 + pY1);
            lacc1 += (pB2 + pB3) + (pY2 + pY3);
            // ---- MMA2 chunk B
#pragma unroll
            for (int nb = 0; nb < 8; nb++) {
                float4 vb = __ldg((const float4*)(qV + 8192 + nb * 128));
                mmatf(O + 4 * nb, pB0, pB2, pB1, pB3, vb.x, vb.y);
                mmatf(O + 4 * nb, pY0, pY2, pY1, pY3, vb.z, vb.w);
            }
        }
        pI1 += TILE_BYTES;
        pV  += TILE_BYTES;
    }

    // quad-reduce row sums
    lacc0 += __shfl_xor_sync(0xffffffffu, lacc0, 1);
    lacc0 += __shfl_xor_sync(0xffffffffu, lacc0, 2);
    lacc1 += __shfl_xor_sync(0xffffffffu, lacc1, 1);
    lacc1 += __shfl_xor_sync(0xffffffffu, lacc1, 2);

    // cross-group combine via smem; z -> Hs in place
    __syncthreads();
    float* Ox = sm + 8192;          // [128][64]
    float* lx = sm + 16384;         // [128]
    int row0 = mrow + g, row1 = row0 + 8;
    if (jo == 1) {
#pragma unroll
        for (int nb = 0; nb < 8; nb++) {
            int c = nb * 8 + 2 * qq;
            *(float2*)(Ox + row0 * 64 + c) = make_float2(O[4 * nb + 0], O[4 * nb + 1]);
            *(float2*)(Ox + row1 * 64 + c) = make_float2(O[4 * nb + 2], O[4 * nb + 3]);
        }
        if (qq == 0) { lx[row0] = lacc0; lx[row1] = lacc1; }
    }
    __syncthreads();
    if (jo == 0) {
        float inv0 = 1.f / (lacc0 + lx[row0]);
        float inv1 = 1.f / (lacc1 + lx[row1]);
#pragma unroll
        for (int nb = 0; nb < 8; nb++) {
            int c = nb * 8 + 2 * qq;
            float2 ob0 = *(const float2*)(Ox + row0 * 64 + c);
            float2 ob1 = *(const float2*)(Ox + row1 * 64 + c);
            float z00 = Hs[row0 * 64 + c]     + (O[4 * nb + 0] + ob0.x) * inv0;
            float z01 = Hs[row0 * 64 + c + 1] + (O[4 * nb + 1] + ob0.y) * inv0;
            float z10 = Hs[row1 * 64 + c]     + (O[4 * nb + 2] + ob1.x) * inv1;
            float z11 = Hs[row1 * 64 + c + 1] + (O[4 * nb + 3] + ob1.y) * inv1;
            *(float2*)(Hs + row0 * 64 + c) = make_float2(z00, z01);
            *(float2*)(Hs + row1 * 64 + c) = make_float2(z10, z11);
        }
    }
    CP_WAIT0();
    __syncthreads();

    // ---- LSTM tail (tensor cores): gates = gx + z @ Whh^T, 3-term split
    {
        uint32_t zhi[16], zlo[16];
#pragma unroll
        for (int ks = 0; ks < 4; ks++) {
            int cb = ks * 16 + 2 * qq;
            hsplit(Hs[row0 * 64 + cb],     Hs[row0 * 64 + cb + 1],
                   zhi[4 * ks + 0], zlo[4 * ks + 0]);
            hsplit(Hs[row1 * 64 + cb],     Hs[row1 * 64 + cb + 1],
                   zhi[4 * ks + 1], zlo[4 * ks + 1]);
            hsplit(Hs[row0 * 64 + cb + 8], Hs[row0 * 64 + cb + 9],
                   zhi[4 * ks + 2], zlo[4 * ks + 2]);
            hsplit(Hs[row1 * 64 + cb + 8], Hs[row1 * 64 + cb + 9],
                   zhi[4 * ks + 3], zlo[4 * ks + 3]);
        }
        // accumulators preloaded with gx: ACC[gate][ub][c4]
        float ACC[4][4][4];
#pragma unroll
        for (int ub = 0; ub < 4; ub++) {
            int u0 = jo * 32 + ub * 8 + 2 * qq;
            int r0 = qbase + row0, r1 = qbase + row1;
            float4 x00 = __ldg((const float4*)&g_gx[(size_t)r0 * 256 + u0 * 4]);
            float4 x01 = __ldg((const float4*)&g_gx[(size_t)r0 * 256 + (u0 + 1) * 4]);
            float4 x10 = __ldg((const float4*)&g_gx[(size_t)r1 * 256 + u0 * 4]);
            float4 x11 = __ldg((const float4*)&g_gx[(size_t)r1 * 256 + (u0 + 1) * 4]);
            ACC[0][ub][0] = x00.x; ACC[0][ub][1] = x01.x;
            ACC[0][ub][2] = x10.x; ACC[0][ub][3] = x11.x;
            ACC[1][ub][0] = x00.y; ACC[1][ub][1] = x01.y;
            ACC[1][ub][2] = x10.y; ACC[1][ub][3] = x11.y;
            ACC[2][ub][0] = x00.z; ACC[2][ub][1] = x01.z;
            ACC[2][ub][2] = x10.z; ACC[2][ub][3] = x11.z;
            ACC[3][ub][0] = x00.w; ACC[3][ub][1] = x01.w;
            ACC[3][ub][2] = x10.w; ACC[3][ub][3] = x11.w;
        }
        // mma: 4 gates x 4 ub x 4 ks x 3 terms = 192
#pragma unroll
        for (int gate = 0; gate < 4; gate++) {
#pragma unroll
            for (int ub = 0; ub < 4; ub++) {
                const uint32_t* wph = Wsm +
                    (((jo * 4 + gate) * 4 + ub) << 8) + g * 8 + qq * 2;
                const uint32_t* wpl = wph + 8192;
#pragma unroll
                for (int ks = 0; ks < 4; ks++) {
                    uint2 bh = *(const uint2*)(wph + ks * 64);
                    uint2 bl = *(const uint2*)(wpl + ks * 64);
                    mmah(ACC[gate][ub], zhi + 4 * ks, bh.x, bh.y);
                    mmah(ACC[gate][ub], zlo + 4 * ks, bh.x, bh.y);
                    mmah(ACC[gate][ub], zhi + 4 * ks, bl.x, bl.y);
                }
            }
        }
        // pointwise LSTM
#pragma unroll
        for (int ub = 0; ub < 4; ub++) {
            int u0 = jo * 32 + ub * 8 + 2 * qq;
#pragma unroll
            for (int k = 0; k < 4; k++) {
                int row = mrow + g + (k >> 1) * 8;
                int u = u0 + (k & 1);
                size_t gq = (size_t)(qbase + row) * 64 + u;
                float gi = ACC[0][ub][k], gf = ACC[1][ub][k];
                float gg = ACC[2][ub][k], go = ACC[3][ub][k];
                float co = first ? 0.f : g_c[gq];
                float cn = sigf(gf) * co + sigf(gi) * tanhf(gg);
                float hn = sigf(go) * tanhf(cn);
                g_c[gq] = cn;
                float hv = hn + __ldg(&q[gq]);
                if (last) out[gq] = hv;
                else g_hhat[gq] = hv;
            }
        }
    }
}

// ---------------- launch ------------------------------------------------------
extern "C" void kernel_launch(void* const* d_in, const int* in_sizes, int n_in,
                              void* d_out, int out_size) {
    const float* support = (const float*)d_in[0];
    const float* queries = (const float*)d_in[1];
    const float* W_ih    = (const float*)d_in[2];
    const float* W_hh    = (const float*)d_in[3];
    const float* b_ih    = (const float*)d_in[4];
    const float* b_hh    = (const float*)d_in[5];
    float* out = (float*)d_out;

    const int smem_bytes = 66560 + 65536;   // 132096
    cudaFuncSetAttribute(attn_kernel, cudaFuncAttributeMaxDynamicSharedMemorySize,
                         smem_bytes);

    prep_kernel<<<NTILES, 256>>>(support);
    prep_w_kernel<<<(256 * 64 + 255) / 256, 256>>>(W_ih, W_hh);
    gx_kernel<<<NQ, 256>>>(queries, b_ih, b_hh);

    for (int step = 0; step < STEPS; step++) {
        int first = (step == 0);
        int last = (step == STEPS - 1);
        attn_kernel<<<NCTA, 512, smem_bytes>>>(queries, out, first, last);
    }
}

// round 17
// speedup vs baseline: 1.8402x; 1.8402x over previous
#include <cuda_runtime.h>
#include <cuda_fp16.h>
#include <cstdint>
#include <math.h>

#define NQ 16384
#define NS 8192
#define D 64
#define NTILES 64          // support tiles of 128 rows
#define STEPS 10
#define NCTA (NQ / 128)    // 128 CTAs, 16 warps each
#define TILE_U32 12288     // 48KB per tile image

// ---------------- device globals (no allocations allowed) -------------------
__device__ float g_hhat[NQ * D];          // h = h_hat + q (pre-added)
__device__ float g_c[NQ * D];
__device__ float g_gx[NQ * 4 * D];        // [q][u][gate i,f,g,o]
__device__ float g_WihT[D * 4 * D];       // [d][row]
// Whh image (fp16 hi/lo) for mma tail:
//   i = jo*4096 + gate*1024 + ub*256 + ks*64 + g*8 + qq*2 + b   (hi; lo at +8192)
__device__ __align__(16) uint32_t g_WhhImg[16384];
// Per tile (12288 u32 = 48KB):
//  I1 (fp16 of s*log2e): u32[ks4][j8][g8][qq4][vec4]            (4096 u32)
//  V (readout, tf32): float4[j8][qq4][fslot64] at +4096          (8192 f32)
//      comp (h*2+pr): support row 16j+8h+2qq+pr, feature f = fslot ^ (qq<<1)
__device__ __align__(16) uint32_t g_B[(size_t)NTILES * TILE_U32];

// ---------------- helpers ----------------------------------------------------
__device__ __forceinline__ uint32_t smem_u32(const void* p) {
    uint32_t a;
    asm("{ .reg .u64 t; cvta.to.shared.u64 t, %1; cvt.u32.u64 %0, t; }"
        : "=r"(a) : "l"(p));
    return a;
}
__device__ __forceinline__ void cp16(uint32_t saddr, const void* g) {
    asm volatile("cp.async.cg.shared.global [%0], [%1], 16;"
                 :: "r"(saddr), "l"(g) : "memory");
}
#define CP_COMMIT() asm volatile("cp.async.commit_group;" ::: "memory")
#define CP_WAIT1()  asm volatile("cp.async.wait_group 1;" ::: "memory")
#define CP_WAIT0()  asm volatile("cp.async.wait_group 0;" ::: "memory")

__device__ __forceinline__ float tf32f(float v) {
    float r;
    asm("cvt.rna.tf32.f32 %0, %1;" : "=f"(r) : "f"(v));
    return r;
}
__device__ __forceinline__ float ex2(float x) {
    float r;
    asm("ex2.approx.f32 %0, %1;" : "=f"(r) : "f"(x));
    return r;
}
__device__ __forceinline__ uint32_t hpack(float v0, float v1) {
    __half2 h = __floats2half2_rn(v0, v1);
    return *reinterpret_cast<uint32_t*>(&h);
}
// exact 2-term fp16 split of (v0, v1)
__device__ __forceinline__ void hsplit(float v0, float v1,
                                       uint32_t& hi, uint32_t& lo) {
    __half2 h = __floats2half2_rn(v0, v1);
    hi = *reinterpret_cast<uint32_t*>(&h);
    float r0 = __half2float(__low2half(h));
    float r1 = __half2float(__high2half(h));
    lo = hpack(v0 - r0, v1 - r1);
}
__device__ __forceinline__ void mmah(float* c, const uint32_t* a,
                                     uint32_t b0, uint32_t b1) {
    asm volatile(
        "mma.sync.aligned.m16n8k16.row.col.f32.f16.f16.f32 "
        "{%0,%1,%2,%3}, {%4,%5,%6,%7}, {%8,%9}, {%0,%1,%2,%3};"
        : "+f"(c[0]), "+f"(c[1]), "+f"(c[2]), "+f"(c[3])
        : "r"(a[0]), "r"(a[1]), "r"(a[2]), "r"(a[3]), "r"(b0), "r"(b1));
}
__device__ __forceinline__ void mmatf(float* c, float a0, float a1, float a2,
                                      float a3, float b0, float b1) {
    asm volatile(
        "mma.sync.aligned.m16n8k8.row.col.f32.tf32.tf32.f32 "
        "{%0,%1,%2,%3}, {%4,%5,%6,%7}, {%8,%9}, {%0,%1,%2,%3};"
        : "+f"(c[0]), "+f"(c[1]), "+f"(c[2]), "+f"(c[3])
        : "r"(__float_as_uint(a0)), "r"(__float_as_uint(a1)),
          "r"(__float_as_uint(a2)), "r"(__float_as_uint(a3)),
          "r"(__float_as_uint(b0)), "r"(__float_as_uint(b1)));
}
__device__ __forceinline__ float sigf(float x) { return 1.f / (1.f + __expf(-x)); }

#define LOG2E 1.4426950408889634f
#define SHIFT2 46.0f   // constant shift in log2 domain (softmax-invariant)

// ---------------- prep: support images --------------------------------------
__global__ void prep_kernel(const float* __restrict__ support) {
    int t = blockIdx.x;
    const float* s = support + (size_t)t * 128 * D;
    uint32_t* dst = g_B + (size_t)t * TILE_U32;
    // I1: single fp16 of s*log2e
    for (int i = threadIdx.x; i < 4096; i += 256) {
        int vec = i & 3, qq = (i >> 2) & 3, g = (i >> 4) & 7;
        int j = (i >> 7) & 7, ks = (i >> 10) & 3;
        int r = 16 * j + g + ((vec & 2) ? 8 : 0);
        int f0 = ks * 16 + ((vec & 1) ? 8 : 0) + 2 * qq;
        dst[i] = hpack(s[r * 64 + f0] * LOG2E, s[r * 64 + f0 + 1] * LOG2E);
    }
    // V: tf32, float4-packed [j][qq][fslot][comp], comp = h*2+pr
    float* vd = (float*)(dst + 4096);
    for (int i = threadIdx.x; i < 8192; i += 256) {
        int comp = i & 3, base = i >> 2;
        int fslot = base & 63, qq = (base >> 6) & 3, j = (base >> 8) & 7;
        int pr = comp & 1, h = comp >> 1;
        int f = fslot ^ (qq << 1);
        int row = 16 * j + 8 * h + 2 * qq + pr;
        vd[i] = tf32f(s[row * 64 + f]);
    }
}

// ---------------- weight prep + gx (once) ------------------------------------
__global__ void prep_w_kernel(const float* __restrict__ W_ih,
                              const float* __restrict__ W_hh) {
    int i = blockIdx.x * blockDim.x + threadIdx.x;
    if (i < 256 * 64) {
        int r = i / D, d = i % D;
        g_WihT[d * 256 + r] = W_ih[i];
    }
    if (i < 8192) {
        int b = i & 1, qq = (i >> 1) & 3, g = (i >> 3) & 7;
        int ks = (i >> 6) & 3, ub = (i >> 8) & 3, gate = (i >> 10) & 3;
        int jo = (i >> 12) & 1;
        int n = gate * 64 + jo * 32 + ub * 8 + g;
        int k0 = ks * 16 + b * 8 + 2 * qq;
        uint32_t hi, lo;
        hsplit(W_hh[n * 64 + k0], W_hh[n * 64 + k0 + 1], hi, lo);
        g_WhhImg[i] = hi;
        g_WhhImg[i + 8192] = lo;
    }
}
__global__ void gx_kernel(const float* __restrict__ q,
                          const float* __restrict__ b_ih,
                          const float* __restrict__ b_hh) {
    __shared__ float qs[D];
    int qi = blockIdx.x, g = threadIdx.x;
    if (g < D) qs[g] = q[qi * D + g];
    __syncthreads();
    float acc = b_ih[g] + b_hh[g];
#pragma unroll
    for (int d = 0; d < D; d++)
        acc = fmaf(qs[d], __ldg(&g_WihT[d * 256 + g]), acc);
    g_gx[qi * 256 + (g & 63) * 4 + (g >> 6)] = acc;
}

// ---------------- fused attention + tensor-core LSTM tail --------------------
// smem: H 32KB | 3 x 48KB tile buffers  = 180224 B (Whh read from L2 in tail)
__global__ void __launch_bounds__(512, 1)
attn_kernel(const float* __restrict__ q, float* __restrict__ out,
            int first, int last) {
    extern __shared__ float sm[];
    float* Hs = sm;
    const int tid = threadIdx.x;
    const int w = tid >> 5, lane = tid & 31;
    const int g = lane >> 2, qq = lane & 3;
    const int wq = w & 7;          // query row-group
    const int jo = w >> 3;         // chunk parity / unit-half group
    const int mrow = wq * 16;
    const int qbase = blockIdx.x * 128;
    const uint32_t sb = smem_u32(sm);

    // H (pre-added h_hat + q stored in g_hhat)
    {
        const float4* src = first
            ? (const float4*)(q + (size_t)qbase * D)
            : (const float4*)(g_hhat + (size_t)qbase * D);
        float4* H4 = (float4*)Hs;
        for (int i = tid; i < 2048; i += 512) H4[i] = src[i];
    }
    __syncthreads();

    // A fragments for MMA1: single fp16 (B image carries log2e)
    uint32_t ahi[16];
    {
        int row0 = mrow + g, row1 = mrow + g + 8;
#pragma unroll
        for (int ks = 0; ks < 4; ks++) {
            int cb = ks * 16 + 2 * qq;
            ahi[4 * ks + 0] = hpack(Hs[row0 * 64 + cb],     Hs[row0 * 64 + cb + 1]);
            ahi[4 * ks + 1] = hpack(Hs[row1 * 64 + cb],     Hs[row1 * 64 + cb + 1]);
            ahi[4 * ks + 2] = hpack(Hs[row0 * 64 + cb + 8], Hs[row0 * 64 + cb + 9]);
            ahi[4 * ks + 3] = hpack(Hs[row1 * 64 + cb + 8], Hs[row1 * 64 + cb + 9]);
        }
    }

    float O[32];
#pragma unroll
    for (int i = 0; i < 32; i++) O[i] = 0.f;
    float lacc0 = 0.f, lacc1 = 0.f;

    // prefetch tiles 0,1 into buffers 0,1 (48KB each: 512 threads x 6 x 16B)
    {
        const char* src = (const char*)g_B + tid * 16;
        uint32_t dst = sb + 32768 + tid * 16;
#pragma unroll
        for (int i = 0; i < 6; i++) cp16(dst + i * 8192, src + i * 8192);
        CP_COMMIT();
#pragma unroll
        for (int i = 0; i < 6; i++)
            cp16(dst + 49152 + i * 8192, src + 49152 + i * 8192);
        CP_COMMIT();
    }

    // fslot per nb is chunk-invariant (float4 index); conflict-free (qq<<1)
    int fsl[8];
#pragma unroll
    for (int nb = 0; nb < 8; nb++) fsl[nb] = (nb * 8 + g) ^ (qq << 1);

    int bufc = 0, bufp = 2;   // consume t%3, prefetch (t+2)%3
#pragma unroll 1
    for (int t = 0; t < NTILES; t++) {
        CP_WAIT1();
        __syncthreads();
        // prefetch t+2 into buf (t+2)%3 (consumed at t-1; top sync protects it)
        if (t + 2 < NTILES) {
            const char* src = (const char*)g_B + (size_t)(t + 2) * 49152 + tid * 16;
            uint32_t dst = sb + 32768 + bufp * 49152 + tid * 16;
#pragma unroll
            for (int i = 0; i < 6; i++) cp16(dst + i * 8192, src + i * 8192);
        }
        CP_COMMIT();

        const uint32_t* B = (const uint32_t*)(sm + 8192) + bufc * TILE_U32;
        const float4* V4 = (const float4*)(B + 4096);

#pragma unroll
        for (int pc = 0; pc < 2; pc++) {
            int jA = jo + 4 * pc;        // chunk A
            int jB = jA + 2;             // chunk B
            // ---- MMA1 for chunk pair: 16 mma, 4 interleaved chains
            float cA0[4] = {0, 0, 0, 0}, cA1[4] = {0, 0, 0, 0};
            float cB0[4] = {0, 0, 0, 0}, cB1[4] = {0, 0, 0, 0};
            int ioffA = jA * 128 + g * 16 + qq * 4;
            int ioffB = jB * 128 + g * 16 + qq * 4;
#pragma unroll
            for (int ks = 0; ks < 4; ks++) {
                uint4 bA = *(const uint4*)(B + ks * 1024 + ioffA);
                uint4 bB = *(const uint4*)(B + ks * 1024 + ioffB);
                mmah(cA0, ahi + 4 * ks, bA.x, bA.y);
                mmah(cB0, ahi + 4 * ks, bB.x, bB.y);
                mmah(cA1, ahi + 4 * ks, bA.z, bA.w);
                mmah(cB1, ahi + 4 * ks, bB.z, bB.w);
            }
            // ---- exp chunk A (exp2; B image pre-scaled by log2e)
            float pA0 = tf32f(ex2(cA0[0] - SHIFT2));
            float pA1 = tf32f(ex2(cA0[1] - SHIFT2));
            float pA2 = tf32f(ex2(cA0[2] - SHIFT2));
            float pA3 = tf32f(ex2(cA0[3] - SHIFT2));
            float pX0 = tf32f(ex2(cA1[0] - SHIFT2));
            float pX1 = tf32f(ex2(cA1[1] - SHIFT2));
            float pX2 = tf32f(ex2(cA1[2] - SHIFT2));
            float pX3 = tf32f(ex2(cA1[3] - SHIFT2));
            lacc0 += (pA0 + pA1) + (pX0 + pX1);
            lacc1 += (pA2 + pA3) + (pX2 + pX3);
            // ---- MMA2 chunk A
            const float4* VpA = V4 + jA * 256 + qq * 64;
#pragma unroll
            for (int nb = 0; nb < 8; nb++) {
                float4 vb = VpA[fsl[nb]];
                mmatf(O + 4 * nb, pA0, pA2, pA1, pA3, vb.x, vb.y);
                mmatf(O + 4 * nb, pX0, pX2, pX1, pX3, vb.z, vb.w);
            }
            // ---- exp chunk B
            float pB0 = tf32f(ex2(cB0[0] - SHIFT2));
            float pB1 = tf32f(ex2(cB0[1] - SHIFT2));
            float pB2 = tf32f(ex2(cB0[2] - SHIFT2));
            float pB3 = tf32f(ex2(cB0[3] - SHIFT2));
            float pY0 = tf32f(ex2(cB1[0] - SHIFT2));
            float pY1 = tf32f(ex2(cB1[1] - SHIFT2));
            float pY2 = tf32f(ex2(cB1[2] - SHIFT2));
            float pY3 = tf32f(ex2(cB1[3] - SHIFT2));
            lacc0 += (pB0 + pB1) + (pY0 + pY1);
            lacc1 += (pB2 + pB3) + (pY2 + pY3);
            // ---- MMA2 chunk B
            const float4* VpB = V4 + jB * 256 + qq * 64;
#pragma unroll
            for (int nb = 0; nb < 8; nb++) {
                float4 vb = VpB[fsl[nb]];
                mmatf(O + 4 * nb, pB0, pB2, pB1, pB3, vb.x, vb.y);
                mmatf(O + 4 * nb, pY0, pY2, pY1, pY3, vb.z, vb.w);
            }
        }
        bufc = (bufc == 2) ? 0 : bufc + 1;
        bufp = (bufp == 2) ? 0 : bufp + 1;
    }

    // quad-reduce row sums
    lacc0 += __shfl_xor_sync(0xffffffffu, lacc0, 1);
    lacc0 += __shfl_xor_sync(0xffffffffu, lacc0, 2);
    lacc1 += __shfl_xor_sync(0xffffffffu, lacc1, 1);
    lacc1 += __shfl_xor_sync(0xffffffffu, lacc1, 2);

    // cross-group combine via smem (alias tile-buffer region); z -> Hs in place
    CP_WAIT0();
    __syncthreads();
    float* Ox = sm + 8192;          // [128][64] (aliases buffer region)
    float* lx = sm + 16384;         // [128]
    int row0 = mrow + g, row1 = row0 + 8;
    if (jo == 1) {
#pragma unroll
        for (int nb = 0; nb < 8; nb++) {
            int c = nb * 8 + 2 * qq;
            *(float2*)(Ox + row0 * 64 + c) = make_float2(O[4 * nb + 0], O[4 * nb + 1]);
            *(float2*)(Ox + row1 * 64 + c) = make_float2(O[4 * nb + 2], O[4 * nb + 3]);
        }
        if (qq == 0) { lx[row0] = lacc0; lx[row1] = lacc1; }
    }
    __syncthreads();
    if (jo == 0) {
        float inv0 = 1.f / (lacc0 + lx[row0]);
        float inv1 = 1.f / (lacc1 + lx[row1]);
#pragma unroll
        for (int nb = 0; nb < 8; nb++) {
            int c = nb * 8 + 2 * qq;
            float2 ob0 = *(const float2*)(Ox + row0 * 64 + c);
            float2 ob1 = *(const float2*)(Ox + row1 * 64 + c);
            float z00 = Hs[row0 * 64 + c]     + (O[4 * nb + 0] + ob0.x) * inv0;
            float z01 = Hs[row0 * 64 + c + 1] + (O[4 * nb + 1] + ob0.y) * inv0;
            float z10 = Hs[row1 * 64 + c]     + (O[4 * nb + 2] + ob1.x) * inv1;
            float z11 = Hs[row1 * 64 + c + 1] + (O[4 * nb + 3] + ob1.y) * inv1;
            *(float2*)(Hs + row0 * 64 + c) = make_float2(z00, z01);
            *(float2*)(Hs + row1 * 64 + c) = make_float2(z10, z11);
        }
    }
    __syncthreads();

    // ---- LSTM tail (tensor cores): gates = gx + z @ Whh^T, 3-term split
    // Whh image streamed from gmem/L2 (coalesced LDG.64, L1-hot after warp 0)
    {
        uint32_t zhi[16], zlo[16];
#pragma unroll
        for (int ks = 0; ks < 4; ks++) {
            int cb = ks * 16 + 2 * qq;
            hsplit(Hs[row0 * 64 + cb],     Hs[row0 * 64 + cb + 1],
                   zhi[4 * ks + 0], zlo[4 * ks + 0]);
            hsplit(Hs[row1 * 64 + cb],     Hs[row1 * 64 + cb + 1],
                   zhi[4 * ks + 1], zlo[4 * ks + 1]);
            hsplit(Hs[row0 * 64 + cb + 8], Hs[row0 * 64 + cb + 9],
                   zhi[4 * ks + 2], zlo[4 * ks + 2]);
            hsplit(Hs[row1 * 64 + cb + 8], Hs[row1 * 64 + cb + 9],
                   zhi[4 * ks + 3], zlo[4 * ks + 3]);
        }
        // accumulators preloaded with gx: ACC[gate][ub][c4]
        float ACC[4][4][4];
#pragma unroll
        for (int ub = 0; ub < 4; ub++) {
            int u0 = jo * 32 + ub * 8 + 2 * qq;
            int r0 = qbase + row0, r1 = qbase + row1;
            float4 x00 = __ldg((const float4*)&g_gx[(size_t)r0 * 256 + u0 * 4]);
            float4 x01 = __ldg((const float4*)&g_gx[(size_t)r0 * 256 + (u0 + 1) * 4]);
            float4 x10 = __ldg((const float4*)&g_gx[(size_t)r1 * 256 + u0 * 4]);
            float4 x11 = __ldg((const float4*)&g_gx[(size_t)r1 * 256 + (u0 + 1) * 4]);
            ACC[0][ub][0] = x00.x; ACC[0][ub][1] = x01.x;
            ACC[0][ub][2] = x10.x; ACC[0][ub][3] = x11.x;
            ACC[1][ub][0] = x00.y; ACC[1][ub][1] = x01.y;
            ACC[1][ub][2] = x10.y; ACC[1][ub][3] = x11.y;
            ACC[2][ub][0] = x00.z; ACC[2][ub][1] = x01.z;
            ACC[2][ub][2] = x10.z; ACC[2][ub][3] = x11.z;
            ACC[3][ub][0] = x00.w; ACC[3][ub][1] = x01.w;
            ACC[3][ub][2] = x10.w; ACC[3][ub][3] = x11.w;
        }
        // mma: 4 gates x 4 ub x 4 ks x 3 terms = 192
#pragma unroll
        for (int gate = 0; gate < 4; gate++) {
#pragma unroll
            for (int ub = 0; ub < 4; ub++) {
                const uint32_t* wph = g_WhhImg +
                    (((jo * 4 + gate) * 4 + ub) << 8) + g * 8 + qq * 2;
                const uint32_t* wpl = wph + 8192;
#pragma unroll
                for (int ks = 0; ks < 4; ks++) {
                    uint2 bh = __ldg((const uint2*)(wph + ks * 64));
                    uint2 bl = __ldg((const uint2*)(wpl + ks * 64));
                    mmah(ACC[gate][ub], zhi + 4 * ks, bh.x, bh.y);
                    mmah(ACC[gate][ub], zlo + 4 * ks, bh.x, bh.y);
                    mmah(ACC[gate][ub], zhi + 4 * ks, bl.x, bl.y);
                }
            }
        }
        // pointwise LSTM
#pragma unroll
        for (int ub = 0; ub < 4; ub++) {
            int u0 = jo * 32 + ub * 8 + 2 * qq;
#pragma unroll
            for (int k = 0; k < 4; k++) {
                int row = mrow + g + (k >> 1) * 8;
                int u = u0 + (k & 1);
                size_t gq = (size_t)(qbase + row) * 64 + u;
                float gi = ACC[0][ub][k], gf = ACC[1][ub][k];
                float gg = ACC[2][ub][k], go = ACC[3][ub][k];
                float co = first ? 0.f : g_c[gq];
                float cn = sigf(gf) * co + sigf(gi) * tanhf(gg);
                float hn = sigf(go) * tanhf(cn);
                g_c[gq] = cn;
                float hv = hn + __ldg(&q[gq]);
                if (last) out[gq] = hv;
                else g_hhat[gq] = hv;
            }
        }
    }
}

// ---------------- launch ------------------------------------------------------
extern "C" void kernel_launch(void* const* d_in, const int* in_sizes, int n_in,
                              void* d_out, int out_size) {
    const float* support = (const float*)d_in[0];
    const float* queries = (const float*)d_in[1];
    const float* W_ih    = (const float*)d_in[2];
    const float* W_hh    = (const float*)d_in[3];
    const float* b_ih    = (const float*)d_in[4];
    const float* b_hh    = (const float*)d_in[5];
    float* out = (float*)d_out;

    const int smem_bytes = 32768 + 3 * 49152;   // 180224
    cudaFuncSetAttribute(attn_kernel, cudaFuncAttributeMaxDynamicSharedMemorySize,
                         smem_bytes);

    prep_kernel<<<NTILES, 256>>>(support);
    prep_w_kernel<<<(256 * 64 + 255) / 256, 256>>>(W_ih, W_hh);
    gx_kernel<<<NQ, 256>>>(queries, b_ih, b_hh);

    for (int step = 0; step < STEPS; step++) {
        int first = (step == 0);
        int last = (step == STEPS - 1);
        attn_kernel<<<NCTA, 512, smem_bytes>>>(queries, out, first, last);
    }
}